// round 3
// baseline (speedup 1.0000x reference)
#include <cuda_runtime.h>
#include <cstdint>

// ---------------------------------------------------------------------------
// GIN block, CSR-based aggregation (atomic-free):
//   CSR build: hist(dst) -> scan -> permute(src sorted by dst)
//   agg[n] = (1+eps)*x[n] + sum_{j in nbrs(n)} x[src_j]
//   h1  = agg @ W1^T + b1            (+ fused column stats)
//   z   = relu(BN1(h1))              (BN1 affine computed in gemm2 prologue)
//   h2  = z @ W2^T + b2              (+ fused column stats, written to out)
//   out = relu(BN2(out))             (BN2 affine computed in bnrelu prologue)
// ---------------------------------------------------------------------------

#define MAXN 50048    // padded to multiple of 128 rows
#define MAXE 1600000

__device__ __align__(16) float g_agg[MAXN * 128];
__device__ __align__(16) float g_h1[MAXN * 128];
__device__ float g_stats[512];   // [sum1(128), sumsq1(128), sum2(128), sumsq2(128)]
__device__ int   g_deg[MAXN + 1];
__device__ int   g_off[MAXN + 1];
__device__ int   g_pos[MAXN + 1];
__device__ int   g_srcsorted[MAXE];
__device__ int   g_is64;         // 1 if edge_index is int64, 0 if int32

// ---------------------------------------------------------------------------
// Detect edge_index dtype. If int64 with node ids < 2^31, every odd int32 word
// (little-endian high half) is zero; for int32 edges those words are node ids.
__global__ void detect_kernel(const int* __restrict__ ei32, int E) {
    __shared__ int nz;
    if (threadIdx.x == 0) nz = 0;
    __syncthreads();
    int pairs = E < 2048 ? E : 2048;
    int cnt = 0;
    for (int i = threadIdx.x; i < pairs; i += blockDim.x)
        if (ei32[2 * i + 1] != 0) cnt++;
    if (cnt) atomicOr(&nz, 1);
    __syncthreads();
    if (threadIdx.x == 0) g_is64 = (nz == 0) ? 1 : 0;
}

// Zero degree histogram + BN stats accumulators.
__global__ void zero_kernel(int N) {
    int i = blockIdx.x * blockDim.x + threadIdx.x;
    if (i <= N) g_deg[i] = 0;
    if (i < 512) g_stats[i] = 0.f;
}

__device__ __forceinline__ int load_idx(const void* ei, long long i) {
    return g_is64 ? (int)((const long long*)ei)[i] : ((const int*)ei)[i];
}

__global__ void hist_kernel(const void* __restrict__ ei, int E) {
    int i = blockIdx.x * blockDim.x + threadIdx.x;
    if (i >= E) return;
    int dst = load_idx(ei, (long long)E + i);
    atomicAdd(&g_deg[dst], 1);
}

// Single-block exclusive scan of g_deg[0..n-1] -> g_off/g_pos, total -> g_off[n].
__global__ void __launch_bounds__(1024) scan_kernel(int n) {
    __shared__ int part[1024];
    int tid = threadIdx.x;
    int chunk = (n + 1023) / 1024;
    int b = tid * chunk;
    int e = b + chunk; if (e > n) e = n;
    int s = 0;
    for (int i = b; i < e; i++) s += g_deg[i];
    part[tid] = s;
    __syncthreads();
    for (int d = 1; d < 1024; d <<= 1) {
        int v = 0;
        if (tid >= d) v = part[tid - d];
        __syncthreads();
        if (tid >= d) part[tid] += v;
        __syncthreads();
    }
    int base = (tid == 0) ? 0 : part[tid - 1];
    for (int i = b; i < e; i++) {
        g_off[i] = base;
        g_pos[i] = base;
        base += g_deg[i];
    }
    if (tid == 0) g_off[n] = part[1023];
}

__global__ void permute_kernel(const void* __restrict__ ei, int E) {
    int i = blockIdx.x * blockDim.x + threadIdx.x;
    if (i >= E) return;
    int src = load_idx(ei, i);
    int dst = load_idx(ei, (long long)E + i);
    int p = atomicAdd(&g_pos[dst], 1);
    g_srcsorted[p] = src;
}

// One warp per node. acc = (1+eps)*x[node] + sum of neighbor rows, one store.
__global__ void aggregate_kernel(const float* __restrict__ x,
                                 const float* __restrict__ eps, int N) {
    int w = (int)((blockIdx.x * blockDim.x + threadIdx.x) >> 5);
    if (w >= N) return;
    int lane = threadIdx.x & 31;
    const float4* x4 = (const float4*)x;
    float s = 1.f + eps[0];
    float4 acc = x4[(size_t)w * 32 + lane];
    acc.x *= s; acc.y *= s; acc.z *= s; acc.w *= s;
    float4 acc2 = make_float4(0.f, 0.f, 0.f, 0.f);
    int j = g_off[w], end = g_off[w + 1];
    for (; j + 3 < end; j += 4) {
        int s0 = g_srcsorted[j + 0];
        int s1 = g_srcsorted[j + 1];
        int s2 = g_srcsorted[j + 2];
        int s3 = g_srcsorted[j + 3];
        float4 v0 = x4[(size_t)s0 * 32 + lane];
        float4 v1 = x4[(size_t)s1 * 32 + lane];
        float4 v2 = x4[(size_t)s2 * 32 + lane];
        float4 v3 = x4[(size_t)s3 * 32 + lane];
        acc.x  += v0.x + v1.x; acc.y  += v0.y + v1.y;
        acc.z  += v0.z + v1.z; acc.w  += v0.w + v1.w;
        acc2.x += v2.x + v3.x; acc2.y += v2.y + v3.y;
        acc2.z += v2.z + v3.z; acc2.w += v2.w + v3.w;
    }
    for (; j < end; j++) {
        int s0 = g_srcsorted[j];
        float4 v0 = x4[(size_t)s0 * 32 + lane];
        acc.x += v0.x; acc.y += v0.y; acc.z += v0.z; acc.w += v0.w;
    }
    acc.x += acc2.x; acc.y += acc2.y; acc.z += acc2.z; acc.w += acc2.w;
    ((float4*)g_agg)[(size_t)w * 32 + lane] = acc;
}

// ---------------------------------------------------------------------------
// SGEMM: C[n,j] = sum_k Ain[n,k] * W[j,k] + bias[j]
// BN1 fold (gemm2 only): Ain = relu(A*a1[k] + c1[k]), a1/c1 computed in
// prologue from g_stats. Fused epilogue: column sum/sumsq atomically added
// to statSum/statSq (valid rows only).
// Block tile 128x128, BK=32, 256 threads, 8x8 register tile.
// ---------------------------------------------------------------------------
template <bool BN1>
__device__ __forceinline__ void gemm_body(const float* __restrict__ A,
                                          const float* __restrict__ W,
                                          const float* __restrict__ bias,
                                          float* __restrict__ C, int N,
                                          const float* __restrict__ gamma,
                                          const float* __restrict__ beta,
                                          float invN,
                                          float* __restrict__ statSum,
                                          float* __restrict__ statSq) {
    __shared__ float As[32][132];
    __shared__ float Ws[32][132];
    __shared__ float s_a[128], s_c[128];
    int tid = threadIdx.x;
    int m0 = blockIdx.x * 128;
    int ty = tid >> 4;   // row group
    int tx = tid & 15;   // col group

    if (BN1) {
        if (tid < 128) {
            float mu  = g_stats[tid] * invN;
            float var = g_stats[128 + tid] * invN - mu * mu;
            float a = gamma[tid] * rsqrtf(var + 1e-5f);
            s_a[tid] = a;
            s_c[tid] = beta[tid] - mu * a;
        }
        __syncthreads();
    }

    float acc[8][8];
#pragma unroll
    for (int r = 0; r < 8; ++r)
#pragma unroll
        for (int c = 0; c < 8; ++c) acc[r][c] = 0.f;

    for (int kk = 0; kk < 128; kk += 32) {
        __syncthreads();
#pragma unroll
        for (int p = 0; p < 4; ++p) {
            int i = tid + p * 256;
            int m = i >> 3;
            int k4 = (i & 7) << 2;
            int gm = m0 + m;
            if (gm >= N) gm = N - 1;  // clamp (rows never stored / counted)
            float4 v = *(const float4*)(A + (size_t)gm * 128 + kk + k4);
            if (BN1) {
                int kg = kk + k4;
                v.x = fmaxf(fmaf(v.x, s_a[kg + 0], s_c[kg + 0]), 0.f);
                v.y = fmaxf(fmaf(v.y, s_a[kg + 1], s_c[kg + 1]), 0.f);
                v.z = fmaxf(fmaf(v.z, s_a[kg + 2], s_c[kg + 2]), 0.f);
                v.w = fmaxf(fmaf(v.w, s_a[kg + 3], s_c[kg + 3]), 0.f);
            }
            As[k4 + 0][m] = v.x; As[k4 + 1][m] = v.y;
            As[k4 + 2][m] = v.z; As[k4 + 3][m] = v.w;
            float4 w = *(const float4*)(W + (size_t)m * 128 + kk + k4);
            Ws[k4 + 0][m] = w.x; Ws[k4 + 1][m] = w.y;
            Ws[k4 + 2][m] = w.z; Ws[k4 + 3][m] = w.w;
        }
        __syncthreads();
#pragma unroll 8
        for (int k = 0; k < 32; ++k) {
            float a[8], b[8];
            *(float4*)(a)     = *(const float4*)(&As[k][ty * 8]);
            *(float4*)(a + 4) = *(const float4*)(&As[k][ty * 8 + 4]);
            *(float4*)(b)     = *(const float4*)(&Ws[k][tx * 8]);
            *(float4*)(b + 4) = *(const float4*)(&Ws[k][tx * 8 + 4]);
#pragma unroll
            for (int r = 0; r < 8; ++r)
#pragma unroll
                for (int c = 0; c < 8; ++c)
                    acc[r][c] = fmaf(a[r], b[c], acc[r][c]);
        }
    }

    float bb[8];
    *(float4*)(bb)     = *(const float4*)(bias + tx * 8);
    *(float4*)(bb + 4) = *(const float4*)(bias + tx * 8 + 4);

    float csum[8], csq[8];
#pragma unroll
    for (int c = 0; c < 8; ++c) { csum[c] = 0.f; csq[c] = 0.f; }

#pragma unroll
    for (int r = 0; r < 8; ++r) {
        int gm = m0 + ty * 8 + r;
        if (gm < N) {
            float v[8];
#pragma unroll
            for (int c = 0; c < 8; ++c) {
                v[c] = acc[r][c] + bb[c];
                csum[c] += v[c];
                csq[c] = fmaf(v[c], v[c], csq[c]);
            }
            *(float4*)(C + (size_t)gm * 128 + tx * 8)     = *(float4*)(v);
            *(float4*)(C + (size_t)gm * 128 + tx * 8 + 4) = *(float4*)(v + 4);
        }
    }

    // Column-stats reduction through smem (reuse As/Ws).
    __syncthreads();
    float (*Ssum)[132] = As;
    float (*Ssq)[132]  = Ws;
#pragma unroll
    for (int c = 0; c < 8; ++c) {
        Ssum[ty >> 1][(ty & 1) ? 0 : 0], 0;  // no-op guard removed below
    }
    // layout: Ssum[ty][col]
#pragma unroll
    for (int c = 0; c < 8; ++c) {
        Ssum[ty & 15][tx * 8 + c] = csum[c];
        Ssq[ty & 15][tx * 8 + c]  = csq[c];
    }
    __syncthreads();
    if (tid < 128) {
        float S = 0.f, Q = 0.f;
#pragma unroll
        for (int t = 0; t < 16; ++t) {
            S += Ssum[t][tid];
            Q += Ssq[t][tid];
        }
        atomicAdd(&statSum[tid], S);
        atomicAdd(&statSq[tid],  Q);
    }
}

__global__ void __launch_bounds__(256)
gemm1_kernel(const float* __restrict__ W, const float* __restrict__ b, int N) {
    gemm_body<false>(g_agg, W, b, g_h1, N, nullptr, nullptr, 0.f,
                     g_stats, g_stats + 128);
}

__global__ void __launch_bounds__(256)
gemm2_kernel(const float* __restrict__ W, const float* __restrict__ b,
             const float* __restrict__ g1, const float* __restrict__ be1,
             float* __restrict__ out, int N, float invN) {
    gemm_body<true>(g_h1, W, b, out, N, g1, be1, invN,
                    g_stats + 256, g_stats + 384);
}

// out = relu(BN2(out)), BN2 affine computed per block from g_stats.
__global__ void __launch_bounds__(256)
bnrelu_kernel(float* __restrict__ out,
              const float* __restrict__ gamma, const float* __restrict__ beta,
              int N, float invN) {
    __shared__ float s_a[128], s_c[128];
    int tid = threadIdx.x;
    if (tid < 128) {
        float mu  = g_stats[256 + tid] * invN;
        float var = g_stats[384 + tid] * invN - mu * mu;
        float a = gamma[tid] * rsqrtf(var + 1e-5f);
        s_a[tid] = a;
        s_c[tid] = beta[tid] - mu * a;
    }
    __syncthreads();
    int c4 = (tid & 31) << 2;  // column of this thread's float4
    float4 a4 = *(const float4*)(s_a + c4);
    float4 c4v = *(const float4*)(s_c + c4);
    int rows_per_iter = gridDim.x * (blockDim.x >> 5);  // float4-rows handled per grid pass
    int r = blockIdx.x * (blockDim.x >> 5) + (tid >> 5);
    float4* o4 = (float4*)out;
    for (; r < N; r += rows_per_iter) {
        size_t idx = (size_t)r * 32 + (tid & 31);
        float4 v = o4[idx];
        v.x = fmaxf(fmaf(v.x, a4.x, c4v.x), 0.f);
        v.y = fmaxf(fmaf(v.y, a4.y, c4v.y), 0.f);
        v.z = fmaxf(fmaf(v.z, a4.z, c4v.z), 0.f);
        v.w = fmaxf(fmaf(v.w, a4.w, c4v.w), 0.f);
        o4[idx] = v;
    }
}

// ---------------------------------------------------------------------------
extern "C" void kernel_launch(void* const* d_in, const int* in_sizes, int n_in,
                              void* d_out, int out_size) {
    const float* x   = (const float*)d_in[0];
    const void*  ei  = d_in[1];
    const float* eps = (const float*)d_in[2];
    const float* W1  = (const float*)d_in[3];
    const float* b1  = (const float*)d_in[4];
    const float* g1  = (const float*)d_in[5];
    const float* be1 = (const float*)d_in[6];
    const float* W2  = (const float*)d_in[7];
    const float* b2  = (const float*)d_in[8];
    const float* g2  = (const float*)d_in[9];
    const float* be2 = (const float*)d_in[10];

    int N = in_sizes[0] / 128;
    int E = in_sizes[1] / 2;
    if (E > MAXE) E = MAXE;
    float* out = (float*)d_out;
    float invN = 1.f / (float)N;

    detect_kernel<<<1, 256>>>((const int*)ei, E);
    zero_kernel<<<(N + 256) / 256, 256>>>(N);
    hist_kernel<<<(E + 255) / 256, 256>>>(ei, E);
    scan_kernel<<<1, 1024>>>(N);
    permute_kernel<<<(E + 255) / 256, 256>>>(ei, E);

    int ablocks = (N * 32 + 255) / 256;  // one warp per node
    aggregate_kernel<<<ablocks, 256>>>(x, eps, N);

    int gblocks = (N + 127) / 128;
    gemm1_kernel<<<gblocks, 256>>>(W1, b1, N);
    gemm2_kernel<<<gblocks, 256>>>(W2, b2, g1, be1, out, N, invN);
    bnrelu_kernel<<<592, 256>>>(out, g2, be2, N, invN);
}

// round 4
// speedup vs baseline: 1.4118x; 1.4118x over previous
#include <cuda_runtime.h>
#include <cstdint>

// ---------------------------------------------------------------------------
// GIN block, CSR-based aggregation (atomic-free aggregate):
//   CSR build: hist(dst) -> 2-level scan -> permute(src sorted by dst)
//   agg[n] = (1+eps)*x[n] + sum_{j in nbrs(n)} x[src_j]
//   h1  = agg @ W1^T + b1            (+ fused column stats)
//   z   = relu(BN1(h1))              (BN1 affine computed in gemm2 prologue)
//   h2  = z @ W2^T + b2              (+ fused column stats, written to out)
//   out = relu(BN2(out))             (BN2 affine computed in bnrelu prologue)
// ---------------------------------------------------------------------------

#define MAXN 50048    // padded to multiple of 128 rows
#define MAXE 1600000

__device__ __align__(16) float g_agg[MAXN * 128];
__device__ __align__(16) float g_h1[MAXN * 128];
__device__ float g_stats[512];   // [sum1(128), sumsq1(128), sum2(128), sumsq2(128)]
__device__ int   g_deg[MAXN + 1];
__device__ int   g_off[MAXN + 1];
__device__ int   g_pos[MAXN + 1];
__device__ int   g_bsum[1024];
__device__ int   g_srcsorted[MAXE];
__device__ int   g_is64;         // 1 if edge_index is int64, 0 if int32

// ---------------------------------------------------------------------------
// Detect edge_index dtype. If int64 with node ids < 2^31, every odd int32 word
// (little-endian high half) is zero; for int32 edges those words are node ids.
__global__ void detect_kernel(const int* __restrict__ ei32, int E) {
    __shared__ int nz;
    if (threadIdx.x == 0) nz = 0;
    __syncthreads();
    int pairs = E < 2048 ? E : 2048;
    int cnt = 0;
    for (int i = threadIdx.x; i < pairs; i += blockDim.x)
        if (ei32[2 * i + 1] != 0) cnt++;
    if (cnt) atomicOr(&nz, 1);
    __syncthreads();
    if (threadIdx.x == 0) g_is64 = (nz == 0) ? 1 : 0;
}

// Zero degree histogram + BN stats accumulators.
__global__ void zero_kernel(int N) {
    int i = blockIdx.x * blockDim.x + threadIdx.x;
    if (i <= N) g_deg[i] = 0;
    if (i < 512) g_stats[i] = 0.f;
}

__device__ __forceinline__ int load_idx(const void* ei, long long i) {
    return g_is64 ? (int)((const long long*)ei)[i] : ((const int*)ei)[i];
}

__global__ void hist_kernel(const void* __restrict__ ei, int E) {
    int i = blockIdx.x * blockDim.x + threadIdx.x;
    if (i >= E) return;
    int dst = load_idx(ei, (long long)E + i);
    atomicAdd(&g_deg[dst], 1);
}

// --------------------- two-level exclusive scan of g_deg --------------------
// Level 1: per-block (1024 elements) sums.
__global__ void __launch_bounds__(256) csr_blocksum(int N) {
    __shared__ int sh[256];
    int tid = threadIdx.x;
    int i0 = blockIdx.x * 1024 + tid * 4;
    int s = 0;
#pragma unroll
    for (int j = 0; j < 4; ++j)
        if (i0 + j < N) s += g_deg[i0 + j];
    sh[tid] = s;
    __syncthreads();
    for (int d = 128; d > 0; d >>= 1) {
        if (tid < d) sh[tid] += sh[tid + d];
        __syncthreads();
    }
    if (tid == 0) g_bsum[blockIdx.x] = sh[0];
}

// Level 2: scan block sums (nb <= 1024), single block, smem only.
__global__ void __launch_bounds__(1024) csr_bscan(int nb, int N) {
    __shared__ int sh[1024];
    int tid = threadIdx.x;
    int v = (tid < nb) ? g_bsum[tid] : 0;
    sh[tid] = v;
    __syncthreads();
    for (int d = 1; d < 1024; d <<= 1) {
        int t = (tid >= d) ? sh[tid - d] : 0;
        __syncthreads();
        sh[tid] += t;
        __syncthreads();
    }
    if (tid < nb) g_bsum[tid] = sh[tid] - v;   // exclusive base per block
    if (tid == 0) {
        g_off[N] = sh[1023];                    // total edge count
        g_pos[N] = sh[1023];
    }
}

// Level 3: per-block offsets = block base + intra-block exclusive scan.
__global__ void __launch_bounds__(256) csr_offsets(int N) {
    __shared__ int sh[256];
    __shared__ int sbase;
    int tid = threadIdx.x;
    if (tid == 0) sbase = g_bsum[blockIdx.x];
    int i0 = blockIdx.x * 1024 + tid * 4;
    int d0 = 0, d1 = 0, d2 = 0, d3 = 0;
    if (i0 + 0 < N) d0 = g_deg[i0 + 0];
    if (i0 + 1 < N) d1 = g_deg[i0 + 1];
    if (i0 + 2 < N) d2 = g_deg[i0 + 2];
    if (i0 + 3 < N) d3 = g_deg[i0 + 3];
    int tsum = d0 + d1 + d2 + d3;
    sh[tid] = tsum;
    __syncthreads();
    for (int d = 1; d < 256; d <<= 1) {
        int t = (tid >= d) ? sh[tid - d] : 0;
        __syncthreads();
        sh[tid] += t;
        __syncthreads();
    }
    int o0 = sh[tid] - tsum + sbase;  // exclusive prefix + block base
    int o1 = o0 + d0, o2 = o1 + d1, o3 = o2 + d2;
    if (i0 + 0 < N) { g_off[i0 + 0] = o0; g_pos[i0 + 0] = o0; }
    if (i0 + 1 < N) { g_off[i0 + 1] = o1; g_pos[i0 + 1] = o1; }
    if (i0 + 2 < N) { g_off[i0 + 2] = o2; g_pos[i0 + 2] = o2; }
    if (i0 + 3 < N) { g_off[i0 + 3] = o3; g_pos[i0 + 3] = o3; }
}

__global__ void permute_kernel(const void* __restrict__ ei, int E) {
    int i = blockIdx.x * blockDim.x + threadIdx.x;
    if (i >= E) return;
    int src = load_idx(ei, i);
    int dst = load_idx(ei, (long long)E + i);
    int p = atomicAdd(&g_pos[dst], 1);
    g_srcsorted[p] = src;
}

// One warp per node. acc = (1+eps)*x[node] + sum of neighbor rows, one store.
__global__ void aggregate_kernel(const float* __restrict__ x,
                                 const float* __restrict__ eps, int N) {
    int w = (int)((blockIdx.x * blockDim.x + threadIdx.x) >> 5);
    if (w >= N) return;
    int lane = threadIdx.x & 31;
    const float4* x4 = (const float4*)x;
    float s = 1.f + eps[0];
    float4 acc = x4[(size_t)w * 32 + lane];
    acc.x *= s; acc.y *= s; acc.z *= s; acc.w *= s;
    float4 acc2 = make_float4(0.f, 0.f, 0.f, 0.f);
    int j = g_off[w], end = g_off[w + 1];
    for (; j + 3 < end; j += 4) {
        int s0 = g_srcsorted[j + 0];
        int s1 = g_srcsorted[j + 1];
        int s2 = g_srcsorted[j + 2];
        int s3 = g_srcsorted[j + 3];
        float4 v0 = x4[(size_t)s0 * 32 + lane];
        float4 v1 = x4[(size_t)s1 * 32 + lane];
        float4 v2 = x4[(size_t)s2 * 32 + lane];
        float4 v3 = x4[(size_t)s3 * 32 + lane];
        acc.x  += v0.x + v1.x; acc.y  += v0.y + v1.y;
        acc.z  += v0.z + v1.z; acc.w  += v0.w + v1.w;
        acc2.x += v2.x + v3.x; acc2.y += v2.y + v3.y;
        acc2.z += v2.z + v3.z; acc2.w += v2.w + v3.w;
    }
    for (; j < end; j++) {
        int s0 = g_srcsorted[j];
        float4 v0 = x4[(size_t)s0 * 32 + lane];
        acc.x += v0.x; acc.y += v0.y; acc.z += v0.z; acc.w += v0.w;
    }
    acc.x += acc2.x; acc.y += acc2.y; acc.z += acc2.z; acc.w += acc2.w;
    ((float4*)g_agg)[(size_t)w * 32 + lane] = acc;
}

// ---------------------------------------------------------------------------
// SGEMM: C[n,j] = sum_k Ain[n,k] * W[j,k] + bias[j]
// BN1 fold (gemm2 only): Ain = relu(A*a1[k] + c1[k]), a1/c1 computed in
// prologue from g_stats. Fused epilogue: column sum/sumsq atomically added
// to statSum/statSq (valid rows only).
// Block tile 128x128, BK=32, 256 threads, 8x8 register tile.
// ---------------------------------------------------------------------------
template <bool BN1>
__device__ __forceinline__ void gemm_body(const float* __restrict__ A,
                                          const float* __restrict__ W,
                                          const float* __restrict__ bias,
                                          float* __restrict__ C, int N,
                                          const float* __restrict__ gamma,
                                          const float* __restrict__ beta,
                                          float invN,
                                          float* __restrict__ statSum,
                                          float* __restrict__ statSq) {
    __shared__ float As[32][132];
    __shared__ float Ws[32][132];
    __shared__ float s_a[128], s_c[128];
    int tid = threadIdx.x;
    int m0 = blockIdx.x * 128;
    int ty = tid >> 4;   // row group
    int tx = tid & 15;   // col group

    if (BN1) {
        if (tid < 128) {
            float mu  = g_stats[tid] * invN;
            float var = g_stats[128 + tid] * invN - mu * mu;
            float a = gamma[tid] * rsqrtf(var + 1e-5f);
            s_a[tid] = a;
            s_c[tid] = beta[tid] - mu * a;
        }
        __syncthreads();
    }

    float acc[8][8];
#pragma unroll
    for (int r = 0; r < 8; ++r)
#pragma unroll
        for (int c = 0; c < 8; ++c) acc[r][c] = 0.f;

    for (int kk = 0; kk < 128; kk += 32) {
        __syncthreads();
#pragma unroll
        for (int p = 0; p < 4; ++p) {
            int i = tid + p * 256;
            int m = i >> 3;
            int k4 = (i & 7) << 2;
            int gm = m0 + m;
            if (gm >= N) gm = N - 1;  // clamp (rows never stored / counted)
            float4 v = *(const float4*)(A + (size_t)gm * 128 + kk + k4);
            if (BN1) {
                int kg = kk + k4;
                v.x = fmaxf(fmaf(v.x, s_a[kg + 0], s_c[kg + 0]), 0.f);
                v.y = fmaxf(fmaf(v.y, s_a[kg + 1], s_c[kg + 1]), 0.f);
                v.z = fmaxf(fmaf(v.z, s_a[kg + 2], s_c[kg + 2]), 0.f);
                v.w = fmaxf(fmaf(v.w, s_a[kg + 3], s_c[kg + 3]), 0.f);
            }
            As[k4 + 0][m] = v.x; As[k4 + 1][m] = v.y;
            As[k4 + 2][m] = v.z; As[k4 + 3][m] = v.w;
            float4 w = *(const float4*)(W + (size_t)m * 128 + kk + k4);
            Ws[k4 + 0][m] = w.x; Ws[k4 + 1][m] = w.y;
            Ws[k4 + 2][m] = w.z; Ws[k4 + 3][m] = w.w;
        }
        __syncthreads();
#pragma unroll 8
        for (int k = 0; k < 32; ++k) {
            float a[8], b[8];
            *(float4*)(a)     = *(const float4*)(&As[k][ty * 8]);
            *(float4*)(a + 4) = *(const float4*)(&As[k][ty * 8 + 4]);
            *(float4*)(b)     = *(const float4*)(&Ws[k][tx * 8]);
            *(float4*)(b + 4) = *(const float4*)(&Ws[k][tx * 8 + 4]);
#pragma unroll
            for (int r = 0; r < 8; ++r)
#pragma unroll
                for (int c = 0; c < 8; ++c)
                    acc[r][c] = fmaf(a[r], b[c], acc[r][c]);
        }
    }

    float bb[8];
    *(float4*)(bb)     = *(const float4*)(bias + tx * 8);
    *(float4*)(bb + 4) = *(const float4*)(bias + tx * 8 + 4);

    float csum[8], csq[8];
#pragma unroll
    for (int c = 0; c < 8; ++c) { csum[c] = 0.f; csq[c] = 0.f; }

#pragma unroll
    for (int r = 0; r < 8; ++r) {
        int gm = m0 + ty * 8 + r;
        if (gm < N) {
            float v[8];
#pragma unroll
            for (int c = 0; c < 8; ++c) {
                v[c] = acc[r][c] + bb[c];
                csum[c] += v[c];
                csq[c] = fmaf(v[c], v[c], csq[c]);
            }
            *(float4*)(C + (size_t)gm * 128 + tx * 8)     = *(float4*)(v);
            *(float4*)(C + (size_t)gm * 128 + tx * 8 + 4) = *(float4*)(v + 4);
        }
    }

    // Column-stats reduction through smem (reuse As/Ws).
    __syncthreads();
    float (*Ssum)[132] = As;
    float (*Ssq)[132]  = Ws;
#pragma unroll
    for (int c = 0; c < 8; ++c) {
        Ssum[ty][tx * 8 + c] = csum[c];
        Ssq[ty][tx * 8 + c]  = csq[c];
    }
    __syncthreads();
    if (tid < 128) {
        float S = 0.f, Q = 0.f;
#pragma unroll
        for (int t = 0; t < 16; ++t) {
            S += Ssum[t][tid];
            Q += Ssq[t][tid];
        }
        atomicAdd(&statSum[tid], S);
        atomicAdd(&statSq[tid],  Q);
    }
}

__global__ void __launch_bounds__(256)
gemm1_kernel(const float* __restrict__ W, const float* __restrict__ b, int N) {
    gemm_body<false>(g_agg, W, b, g_h1, N, nullptr, nullptr, 0.f,
                     g_stats, g_stats + 128);
}

__global__ void __launch_bounds__(256)
gemm2_kernel(const float* __restrict__ W, const float* __restrict__ b,
             const float* __restrict__ g1, const float* __restrict__ be1,
             float* __restrict__ out, int N, float invN) {
    gemm_body<true>(g_h1, W, b, out, N, g1, be1, invN,
                    g_stats + 256, g_stats + 384);
}

// out = relu(BN2(out)), BN2 affine computed per block from g_stats.
__global__ void __launch_bounds__(256)
bnrelu_kernel(float* __restrict__ out,
              const float* __restrict__ gamma, const float* __restrict__ beta,
              int N, float invN) {
    __shared__ float s_a[128], s_c[128];
    int tid = threadIdx.x;
    if (tid < 128) {
        float mu  = g_stats[256 + tid] * invN;
        float var = g_stats[384 + tid] * invN - mu * mu;
        float a = gamma[tid] * rsqrtf(var + 1e-5f);
        s_a[tid] = a;
        s_c[tid] = beta[tid] - mu * a;
    }
    __syncthreads();
    int c4 = (tid & 31) << 2;  // column of this thread's float4
    float4 a4 = *(const float4*)(s_a + c4);
    float4 c4v = *(const float4*)(s_c + c4);
    int rows_per_iter = gridDim.x * (blockDim.x >> 5);
    int r = blockIdx.x * (blockDim.x >> 5) + (tid >> 5);
    float4* o4 = (float4*)out;
    for (; r < N; r += rows_per_iter) {
        size_t idx = (size_t)r * 32 + (tid & 31);
        float4 v = o4[idx];
        v.x = fmaxf(fmaf(v.x, a4.x, c4v.x), 0.f);
        v.y = fmaxf(fmaf(v.y, a4.y, c4v.y), 0.f);
        v.z = fmaxf(fmaf(v.z, a4.z, c4v.z), 0.f);
        v.w = fmaxf(fmaf(v.w, a4.w, c4v.w), 0.f);
        o4[idx] = v;
    }
}

// ---------------------------------------------------------------------------
extern "C" void kernel_launch(void* const* d_in, const int* in_sizes, int n_in,
                              void* d_out, int out_size) {
    const float* x   = (const float*)d_in[0];
    const void*  ei  = d_in[1];
    const float* eps = (const float*)d_in[2];
    const float* W1  = (const float*)d_in[3];
    const float* b1  = (const float*)d_in[4];
    const float* g1  = (const float*)d_in[5];
    const float* be1 = (const float*)d_in[6];
    const float* W2  = (const float*)d_in[7];
    const float* b2  = (const float*)d_in[8];
    const float* g2  = (const float*)d_in[9];
    const float* be2 = (const float*)d_in[10];

    int N = in_sizes[0] / 128;
    int E = in_sizes[1] / 2;
    if (E > MAXE) E = MAXE;
    float* out = (float*)d_out;
    float invN = 1.f / (float)N;
    int nb = (N + 1023) / 1024;  // scan blocks

    detect_kernel<<<1, 256>>>((const int*)ei, E);
    zero_kernel<<<(N + 256) / 256, 256>>>(N);
    hist_kernel<<<(E + 255) / 256, 256>>>(ei, E);
    csr_blocksum<<<nb, 256>>>(N);
    csr_bscan<<<1, 1024>>>(nb, N);
    csr_offsets<<<nb, 256>>>(N);
    permute_kernel<<<(E + 255) / 256, 256>>>(ei, E);

    int ablocks = (N * 32 + 255) / 256;  // one warp per node
    aggregate_kernel<<<ablocks, 256>>>(x, eps, N);

    int gblocks = (N + 127) / 128;
    gemm1_kernel<<<gblocks, 256>>>(W1, b1, N);
    gemm2_kernel<<<gblocks, 256>>>(W2, b2, g1, be1, out, N, invN);
    bnrelu_kernel<<<592, 256>>>(out, g2, be2, N, invN);
}

// round 7
// speedup vs baseline: 1.5444x; 1.0939x over previous
#include <cuda_runtime.h>
#include <cstdint>

// ---------------------------------------------------------------------------
// GIN block. CSR aggregation + 3xTF32 mma.sync tensor-core GEMMs (sm_80+ PTX;
// tcgen05 is unavailable under the harness's compute_103 PTX target).
//   agg = (1+eps)*x + scatter_add(x[src] -> dst)     (CSR gather, atomic-free)
//   h1  = agg @ W1^T + b1                            (mma.sync, fused stats)
//   z   = relu(BN1(h1))                              (folded into gemm2 A load)
//   h2  = z @ W2^T + b2                              (mma.sync, fused stats)
//   out = relu(BN2(h2))
// NOTE: __device__ symbols (g_agg/g_h1/g_stats) must ONLY be referenced from
// device code. Passing them as host-side kernel args binds the host shadow
// (ATS makes it dereferenceable on GB300 -> silent wrong results, R6 bug).
// ---------------------------------------------------------------------------

#define MAXN 50048
#define MAXE 1600000

__device__ __align__(16) float g_agg[MAXN * 128];
__device__ __align__(16) float g_h1[MAXN * 128];
__device__ float g_stats[512];   // [sum1, sumsq1, sum2, sumsq2] x 128
__device__ int   g_deg[MAXN + 1];
__device__ int   g_off[MAXN + 1];
__device__ int   g_pos[MAXN + 1];
__device__ int   g_bsum[1024];
__device__ int   g_srcsorted[MAXE];
__device__ int   g_is64;

// ---------------------------------------------------------------------------
__global__ void detect_kernel(const int* __restrict__ ei32, int E) {
    __shared__ int nz;
    if (threadIdx.x == 0) nz = 0;
    __syncthreads();
    int pairs = E < 2048 ? E : 2048;
    int cnt = 0;
    for (int i = threadIdx.x; i < pairs; i += blockDim.x)
        if (ei32[2 * i + 1] != 0) cnt++;
    if (cnt) atomicOr(&nz, 1);
    __syncthreads();
    if (threadIdx.x == 0) g_is64 = (nz == 0) ? 1 : 0;
}

__global__ void zero_kernel(int N) {
    int i = blockIdx.x * blockDim.x + threadIdx.x;
    if (i <= N) g_deg[i] = 0;
    if (i < 512) g_stats[i] = 0.f;
}

__device__ __forceinline__ int load_idx(const void* ei, long long i) {
    return g_is64 ? (int)((const long long*)ei)[i] : ((const int*)ei)[i];
}

__global__ void hist_kernel(const void* __restrict__ ei, int E) {
    int i = blockIdx.x * blockDim.x + threadIdx.x;
    if (i >= E) return;
    atomicAdd(&g_deg[load_idx(ei, (long long)E + i)], 1);
}

__global__ void __launch_bounds__(256) csr_blocksum(int N) {
    __shared__ int sh[256];
    int tid = threadIdx.x;
    int i0 = blockIdx.x * 1024 + tid * 4;
    int s = 0;
#pragma unroll
    for (int j = 0; j < 4; ++j)
        if (i0 + j < N) s += g_deg[i0 + j];
    sh[tid] = s;
    __syncthreads();
    for (int d = 128; d > 0; d >>= 1) {
        if (tid < d) sh[tid] += sh[tid + d];
        __syncthreads();
    }
    if (tid == 0) g_bsum[blockIdx.x] = sh[0];
}

__global__ void __launch_bounds__(1024) csr_bscan(int nb, int N) {
    __shared__ int sh[1024];
    int tid = threadIdx.x;
    int v = (tid < nb) ? g_bsum[tid] : 0;
    sh[tid] = v;
    __syncthreads();
    for (int d = 1; d < 1024; d <<= 1) {
        int t = (tid >= d) ? sh[tid - d] : 0;
        __syncthreads();
        sh[tid] += t;
        __syncthreads();
    }
    if (tid < nb) g_bsum[tid] = sh[tid] - v;
    if (tid == 0) { g_off[N] = sh[1023]; g_pos[N] = sh[1023]; }
}

__global__ void __launch_bounds__(256) csr_offsets(int N) {
    __shared__ int sh[256];
    __shared__ int sbase;
    int tid = threadIdx.x;
    if (tid == 0) sbase = g_bsum[blockIdx.x];
    int i0 = blockIdx.x * 1024 + tid * 4;
    int d0 = 0, d1 = 0, d2 = 0, d3 = 0;
    if (i0 + 0 < N) d0 = g_deg[i0 + 0];
    if (i0 + 1 < N) d1 = g_deg[i0 + 1];
    if (i0 + 2 < N) d2 = g_deg[i0 + 2];
    if (i0 + 3 < N) d3 = g_deg[i0 + 3];
    int tsum = d0 + d1 + d2 + d3;
    sh[tid] = tsum;
    __syncthreads();
    for (int d = 1; d < 256; d <<= 1) {
        int t = (tid >= d) ? sh[tid - d] : 0;
        __syncthreads();
        sh[tid] += t;
        __syncthreads();
    }
    int o0 = sh[tid] - tsum + sbase;
    int o1 = o0 + d0, o2 = o1 + d1, o3 = o2 + d2;
    if (i0 + 0 < N) { g_off[i0 + 0] = o0; g_pos[i0 + 0] = o0; }
    if (i0 + 1 < N) { g_off[i0 + 1] = o1; g_pos[i0 + 1] = o1; }
    if (i0 + 2 < N) { g_off[i0 + 2] = o2; g_pos[i0 + 2] = o2; }
    if (i0 + 3 < N) { g_off[i0 + 3] = o3; g_pos[i0 + 3] = o3; }
}

__global__ void permute_kernel(const void* __restrict__ ei, int E) {
    int i = blockIdx.x * blockDim.x + threadIdx.x;
    if (i >= E) return;
    int src = load_idx(ei, i);
    int dst = load_idx(ei, (long long)E + i);
    g_srcsorted[atomicAdd(&g_pos[dst], 1)] = src;
}

// One warp per node: sum neighbor rows + (1+eps)*own row, single store.
__global__ void aggregate_kernel(const float* __restrict__ x,
                                 const float* __restrict__ eps, int N) {
    int w = (int)((blockIdx.x * blockDim.x + threadIdx.x) >> 5);
    if (w >= N) return;
    int lane = threadIdx.x & 31;
    const float4* x4 = (const float4*)x;
    float s = 1.f + eps[0];
    float4 acc = x4[(size_t)w * 32 + lane];
    acc.x *= s; acc.y *= s; acc.z *= s; acc.w *= s;
    float4 acc2 = make_float4(0.f, 0.f, 0.f, 0.f);
    int j = g_off[w], end = g_off[w + 1];
    for (; j + 3 < end; j += 4) {
        int s0 = g_srcsorted[j + 0];
        int s1 = g_srcsorted[j + 1];
        int s2 = g_srcsorted[j + 2];
        int s3 = g_srcsorted[j + 3];
        float4 v0 = x4[(size_t)s0 * 32 + lane];
        float4 v1 = x4[(size_t)s1 * 32 + lane];
        float4 v2 = x4[(size_t)s2 * 32 + lane];
        float4 v3 = x4[(size_t)s3 * 32 + lane];
        acc.x  += v0.x + v1.x; acc.y  += v0.y + v1.y;
        acc.z  += v0.z + v1.z; acc.w  += v0.w + v1.w;
        acc2.x += v2.x + v3.x; acc2.y += v2.y + v3.y;
        acc2.z += v2.z + v3.z; acc2.w += v2.w + v3.w;
    }
    for (; j < end; j++) {
        float4 v0 = x4[(size_t)g_srcsorted[j] * 32 + lane];
        acc.x += v0.x; acc.y += v0.y; acc.z += v0.z; acc.w += v0.w;
    }
    acc.x += acc2.x; acc.y += acc2.y; acc.z += acc2.z; acc.w += acc2.w;
    ((float4*)g_agg)[(size_t)w * 32 + lane] = acc;
}

// ---------------------------------------------------------------------------
// 3xTF32 tensor-core GEMM: D[m,n] = sum_k Ain[m,k]*W[n,k] + bias[n]
// A kept fp32 in smem (split per fragment load); W pre-split into Bhi/Blo
// tf32. mma.sync m16n8k8 row.col. Stride 132 floats. CTA: 128x128 tile,
// 8 warps = 4 row-groups(32) x 2 col-groups(64). Fused BN column stats.
// BN1=false: A=g_agg, C=g_h1, stats -> g_stats[0/128]
// BN1=true:  A=g_h1 (BN1+ReLU folded), C=outp, stats -> g_stats[256/384]
// ---------------------------------------------------------------------------
#define SMO_A     0                     // float A[128][132]
#define SMO_BH    67584                 // uint32 Bhi[128][132]
#define SMO_BL    135168                // uint32 Blo[128][132]
#define SMO_BIAS  202752                // float[128]
#define SMO_SA    203264                // float[128]
#define SMO_SC    203776                // float[128]
#define SMO_SS    204288                // float[128]
#define SMO_SQ    204800                // float[128]
#define SMEM_GEMM 205312

__device__ __forceinline__ uint32_t f2tf32(float x) {
    uint32_t r;
    asm("cvt.rna.tf32.f32 %0, %1;" : "=r"(r) : "f"(x));
    return r;
}

__device__ __forceinline__ void mma_tf32(float* d, const uint32_t* a,
                                         uint32_t b0, uint32_t b1) {
    asm volatile(
        "mma.sync.aligned.m16n8k8.row.col.f32.tf32.tf32.f32 "
        "{%0,%1,%2,%3}, {%4,%5,%6,%7}, {%8,%9}, {%0,%1,%2,%3};"
        : "+f"(d[0]), "+f"(d[1]), "+f"(d[2]), "+f"(d[3])
        : "r"(a[0]), "r"(a[1]), "r"(a[2]), "r"(a[3]), "r"(b0), "r"(b1));
}

template <bool BN1>
__global__ void __launch_bounds__(256, 1)
gemm_mma(const float* __restrict__ W, const float* __restrict__ bias,
         const float* __restrict__ gamma, const float* __restrict__ beta,
         float* __restrict__ outp, int N, float invN) {
    // Bind device symbols HERE (device code), never from host.
    const float* A  = BN1 ? g_h1 : g_agg;
    float* C        = BN1 ? outp : g_h1;
    float* statSum  = BN1 ? (g_stats + 256) : g_stats;
    float* statSq   = BN1 ? (g_stats + 384) : (g_stats + 128);

    extern __shared__ __align__(16) char smem[];
    float*    As = (float*)(smem + SMO_A);
    uint32_t* Bh = (uint32_t*)(smem + SMO_BH);
    uint32_t* Bl = (uint32_t*)(smem + SMO_BL);
    float* sbias = (float*)(smem + SMO_BIAS);
    float* s_a   = (float*)(smem + SMO_SA);
    float* s_c   = (float*)(smem + SMO_SC);
    float* sS    = (float*)(smem + SMO_SS);
    float* sQ    = (float*)(smem + SMO_SQ);

    int tid = threadIdx.x, wid = tid >> 5, lane = tid & 31;
    int wr = wid >> 1;        // 0..3 : rows wr*32 .. +32
    int wc = wid & 1;         // 0..1 : cols wc*64 .. +64
    int gid = lane >> 2;      // 0..7
    int tig = lane & 3;       // 0..3
    int m0 = blockIdx.x * 128;

    if (tid < 128) {
        sbias[tid] = bias[tid];
        sS[tid] = 0.f;
        sQ[tid] = 0.f;
        if (BN1) {
            float mu  = g_stats[tid] * invN;
            float var = g_stats[128 + tid] * invN - mu * mu;
            float a = gamma[tid] * rsqrtf(var + 1e-5f);
            s_a[tid] = a;
            s_c[tid] = beta[tid] - mu * a;
        }
    }
    __syncthreads();   // s_a/s_c ready before A load

    // ---- load A tile (fp32, BN1+ReLU folded) ----
#pragma unroll
    for (int it = 0; it < 16; ++it) {
        int idx = tid + it * 256;        // 0..4095
        int row = idx >> 5;              // 0..127
        int k0  = (idx & 31) << 2;       // 0..124
        int gm = m0 + row; if (gm >= N) gm = N - 1;
        float4 v = *(const float4*)(A + (size_t)gm * 128 + k0);
        if (BN1) {
            v.x = fmaxf(fmaf(v.x, s_a[k0 + 0], s_c[k0 + 0]), 0.f);
            v.y = fmaxf(fmaf(v.y, s_a[k0 + 1], s_c[k0 + 1]), 0.f);
            v.z = fmaxf(fmaf(v.z, s_a[k0 + 2], s_c[k0 + 2]), 0.f);
            v.w = fmaxf(fmaf(v.w, s_a[k0 + 3], s_c[k0 + 3]), 0.f);
        }
        *(float4*)(As + row * 132 + k0) = v;
    }
    // ---- load W, split into Bhi/Blo tf32 ----
#pragma unroll
    for (int it = 0; it < 16; ++it) {
        int idx = tid + it * 256;
        int row = idx >> 5;              // n
        int k0  = (idx & 31) << 2;
        float4 v = *(const float4*)(W + (size_t)row * 128 + k0);
        float f[4] = {v.x, v.y, v.z, v.w};
        uint32_t hi[4], lo[4];
#pragma unroll
        for (int j = 0; j < 4; ++j) {
            hi[j] = f2tf32(f[j]);
            lo[j] = f2tf32(f[j] - __uint_as_float(hi[j]));
        }
        *(uint4*)(Bh + row * 132 + k0) = make_uint4(hi[0], hi[1], hi[2], hi[3]);
        *(uint4*)(Bl + row * 132 + k0) = make_uint4(lo[0], lo[1], lo[2], lo[3]);
    }
    __syncthreads();

    // ---- mainloop ----
    float acc[2][8][4];
#pragma unroll
    for (int mt = 0; mt < 2; ++mt)
#pragma unroll
        for (int nt = 0; nt < 8; ++nt)
#pragma unroll
            for (int r = 0; r < 4; ++r) acc[mt][nt][r] = 0.f;

#pragma unroll 4
    for (int ks = 0; ks < 16; ++ks) {
        int k0 = ks * 8;
        uint32_t ahi[2][4], alo[2][4];
#pragma unroll
        for (int mt = 0; mt < 2; ++mt) {
            int r0 = wr * 32 + mt * 16 + gid;
            float a0 = As[r0 * 132 + k0 + tig];
            float a1 = As[(r0 + 8) * 132 + k0 + tig];
            float a2 = As[r0 * 132 + k0 + tig + 4];
            float a3 = As[(r0 + 8) * 132 + k0 + tig + 4];
            ahi[mt][0] = f2tf32(a0); alo[mt][0] = f2tf32(a0 - __uint_as_float(ahi[mt][0]));
            ahi[mt][1] = f2tf32(a1); alo[mt][1] = f2tf32(a1 - __uint_as_float(ahi[mt][1]));
            ahi[mt][2] = f2tf32(a2); alo[mt][2] = f2tf32(a2 - __uint_as_float(ahi[mt][2]));
            ahi[mt][3] = f2tf32(a3); alo[mt][3] = f2tf32(a3 - __uint_as_float(ahi[mt][3]));
        }
#pragma unroll
        for (int nt = 0; nt < 8; ++nt) {
            int n = wc * 64 + nt * 8 + gid;
            uint32_t bh0 = Bh[n * 132 + k0 + tig];
            uint32_t bh1 = Bh[n * 132 + k0 + tig + 4];
            uint32_t bl0 = Bl[n * 132 + k0 + tig];
            uint32_t bl1 = Bl[n * 132 + k0 + tig + 4];
#pragma unroll
            for (int mt = 0; mt < 2; ++mt) {
                mma_tf32(acc[mt][nt], ahi[mt], bh0, bh1);
                mma_tf32(acc[mt][nt], ahi[mt], bl0, bl1);
                mma_tf32(acc[mt][nt], alo[mt], bh0, bh1);
            }
        }
    }

    // ---- epilogue: bias add, store, fused column stats ----
    float ls[16], lq[16];
#pragma unroll
    for (int i = 0; i < 16; ++i) { ls[i] = 0.f; lq[i] = 0.f; }

#pragma unroll
    for (int mt = 0; mt < 2; ++mt) {
        int grow0 = m0 + wr * 32 + mt * 16 + gid;
        int grow1 = grow0 + 8;
        bool v0 = grow0 < N, v1 = grow1 < N;
#pragma unroll
        for (int nt = 0; nt < 8; ++nt) {
            int gcol = wc * 64 + nt * 8 + tig * 2;
            float d0 = acc[mt][nt][0] + sbias[gcol];
            float d1 = acc[mt][nt][1] + sbias[gcol + 1];
            float d2 = acc[mt][nt][2] + sbias[gcol];
            float d3 = acc[mt][nt][3] + sbias[gcol + 1];
            if (v0) {
                *(float2*)(C + (size_t)grow0 * 128 + gcol) = make_float2(d0, d1);
                ls[nt * 2]     += d0; lq[nt * 2]     = fmaf(d0, d0, lq[nt * 2]);
                ls[nt * 2 + 1] += d1; lq[nt * 2 + 1] = fmaf(d1, d1, lq[nt * 2 + 1]);
            }
            if (v1) {
                *(float2*)(C + (size_t)grow1 * 128 + gcol) = make_float2(d2, d3);
                ls[nt * 2]     += d2; lq[nt * 2]     = fmaf(d2, d2, lq[nt * 2]);
                ls[nt * 2 + 1] += d3; lq[nt * 2 + 1] = fmaf(d3, d3, lq[nt * 2 + 1]);
            }
        }
    }
    // reduce across the 8 row-owning lanes (gid) of the warp
#pragma unroll
    for (int d = 4; d < 32; d <<= 1) {
#pragma unroll
        for (int i = 0; i < 16; ++i) {
            ls[i] += __shfl_xor_sync(0xFFFFFFFFu, ls[i], d);
            lq[i] += __shfl_xor_sync(0xFFFFFFFFu, lq[i], d);
        }
    }
    if (gid == 0) {
#pragma unroll
        for (int i = 0; i < 16; ++i) {
            int col = wc * 64 + (i >> 1) * 8 + tig * 2 + (i & 1);
            atomicAdd(&sS[col], ls[i]);
            atomicAdd(&sQ[col], lq[i]);
        }
    }
    __syncthreads();
    if (tid < 128) {
        atomicAdd(&statSum[tid], sS[tid]);
        atomicAdd(&statSq[tid],  sQ[tid]);
    }
}

// out = relu(BN2(out)), BN2 affine computed per block from g_stats.
__global__ void __launch_bounds__(256)
bnrelu_kernel(float* __restrict__ out,
              const float* __restrict__ gamma, const float* __restrict__ beta,
              int N, float invN) {
    __shared__ float s_a[128], s_c[128];
    int tid = threadIdx.x;
    if (tid < 128) {
        float mu  = g_stats[256 + tid] * invN;
        float var = g_stats[384 + tid] * invN - mu * mu;
        float a = gamma[tid] * rsqrtf(var + 1e-5f);
        s_a[tid] = a;
        s_c[tid] = beta[tid] - mu * a;
    }
    __syncthreads();
    int c4 = (tid & 31) << 2;
    float4 a4  = *(const float4*)(s_a + c4);
    float4 c4v = *(const float4*)(s_c + c4);
    int rows_per_iter = gridDim.x * (blockDim.x >> 5);
    int r = blockIdx.x * (blockDim.x >> 5) + (tid >> 5);
    float4* o4 = (float4*)out;
    for (; r < N; r += rows_per_iter) {
        size_t idx = (size_t)r * 32 + (tid & 31);
        float4 v = o4[idx];
        v.x = fmaxf(fmaf(v.x, a4.x, c4v.x), 0.f);
        v.y = fmaxf(fmaf(v.y, a4.y, c4v.y), 0.f);
        v.z = fmaxf(fmaf(v.z, a4.z, c4v.z), 0.f);
        v.w = fmaxf(fmaf(v.w, a4.w, c4v.w), 0.f);
        o4[idx] = v;
    }
}

// ---------------------------------------------------------------------------
extern "C" void kernel_launch(void* const* d_in, const int* in_sizes, int n_in,
                              void* d_out, int out_size) {
    const float* x   = (const float*)d_in[0];
    const void*  ei  = d_in[1];
    const float* eps = (const float*)d_in[2];
    const float* W1  = (const float*)d_in[3];
    const float* b1  = (const float*)d_in[4];
    const float* g1  = (const float*)d_in[5];
    const float* be1 = (const float*)d_in[6];
    const float* W2  = (const float*)d_in[7];
    const float* b2  = (const float*)d_in[8];
    const float* g2  = (const float*)d_in[9];
    const float* be2 = (const float*)d_in[10];

    int N = in_sizes[0] / 128;
    int E = in_sizes[1] / 2;
    if (E > MAXE) E = MAXE;
    float* out = (float*)d_out;
    float invN = 1.f / (float)N;
    int nb = (N + 1023) / 1024;

    cudaFuncSetAttribute(gemm_mma<false>,
                         cudaFuncAttributeMaxDynamicSharedMemorySize, SMEM_GEMM);
    cudaFuncSetAttribute(gemm_mma<true>,
                         cudaFuncAttributeMaxDynamicSharedMemorySize, SMEM_GEMM);

    detect_kernel<<<1, 256>>>((const int*)ei, E);
    zero_kernel<<<(N + 256) / 256, 256>>>(N);
    hist_kernel<<<(E + 255) / 256, 256>>>(ei, E);
    csr_blocksum<<<nb, 256>>>(N);
    csr_bscan<<<1, 1024>>>(nb, N);
    csr_offsets<<<nb, 256>>>(N);
    permute_kernel<<<(E + 255) / 256, 256>>>(ei, E);

    int ablocks = (N * 32 + 255) / 256;
    aggregate_kernel<<<ablocks, 256>>>(x, eps, N);

    int gblocks = (N + 127) / 128;
    gemm_mma<false><<<gblocks, 256, SMEM_GEMM>>>(W1, b1, nullptr, nullptr,
                                                 nullptr, N, invN);
    gemm_mma<true><<<gblocks, 256, SMEM_GEMM>>>(W2, b2, g1, be1,
                                                out, N, invN);
    bnrelu_kernel<<<592, 256>>>(out, g2, be2, N, invN);
}